// round 1
// baseline (speedup 1.0000x reference)
#include <cuda_runtime.h>
#include <cstddef>
#include <cstdint>

// Problem dims (fixed by the benchmark)
#define BB 128
#define TT 512
#define DD 512
#define UU 1024
#define GG 4096   // 4*U
#define OO 512

// ---------------- scratch (static device globals; no runtime allocation) ----
__device__ float g_xz[(size_t)BB * TT * GG];   // [B][T][4U]  precomputed x@kernel+bias
__device__ float g_hs[(size_t)BB * TT * UU];   // [B][T][U]   all hidden states
__device__ float g_h[2][BB * UU];              // double-buffered h
__device__ float g_c[BB * UU];                 // cell state

// ---------------- packed f32x2 helpers (sm_10x) -----------------------------
__device__ __forceinline__ void fma2(unsigned long long &acc,
                                     unsigned long long a,
                                     unsigned long long b) {
    asm("fma.rn.f32x2 %0, %1, %2, %3;" : "=l"(acc) : "l"(a), "l"(b), "l"(acc));
}
__device__ __forceinline__ unsigned long long splat2(float x) {
    unsigned long long r;
    unsigned u = __float_as_uint(x);
    asm("mov.b64 %0, {%1, %1};" : "=l"(r) : "r"(u));
    return r;
}
__device__ __forceinline__ float lo2(unsigned long long v) {
    return __uint_as_float((unsigned)v);
}
__device__ __forceinline__ float hi2(unsigned long long v) {
    return __uint_as_float((unsigned)(v >> 32));
}
__device__ __forceinline__ float sigmoidf_(float x) {
    return 1.0f / (1.0f + __expf(-x));
}

// ---------------- init: copy h0/c0 into state buffers -----------------------
__global__ __launch_bounds__(256) void init_state(const float* __restrict__ h0,
                                                  const float* __restrict__ c0) {
    int i = blockIdx.x * 256 + threadIdx.x;   // grid covers 128*1024
    g_h[0][i] = h0[i];
    g_c[i]    = c0[i];
}

// ---------------- generic GEMM: C[M,N] = A[M,K] @ B[K,N] + bias[N] ----------
// BM=128, BN=128, BK=16, 256 threads, 8x8 microtile via f32x2.
// Requires M%128==0, N%128==0, K%16==0 (true for both uses).
__global__ __launch_bounds__(256) void gemm_bias_kernel(
    const float* __restrict__ A, const float* __restrict__ Bm,
    const float* __restrict__ bias, float* __restrict__ C,
    int N, int K) {
    __shared__ float Ash[16][132];   // [k][row], padded to dodge bank conflicts
    __shared__ float Bsh[16][128];   // [k][col]

    const int tid = threadIdx.x;
    const int m0 = blockIdx.y * 128;
    const int n0 = blockIdx.x * 128;
    const int tx = tid & 15;         // col group (8 cols)
    const int ty = tid >> 4;         // row group (8 rows)

    unsigned long long acc[8][4];
#pragma unroll
    for (int i = 0; i < 8; i++)
#pragma unroll
        for (int p = 0; p < 4; p++) acc[i][p] = 0ULL;

    for (int k0 = 0; k0 < K; k0 += 16) {
        // A tile: 128 rows x 16 cols = 512 float4, 2 per thread (transposed store)
#pragma unroll
        for (int i = 0; i < 2; i++) {
            int f4 = tid + i * 256;
            int row = f4 >> 2;
            int c4 = (f4 & 3) * 4;
            float4 v = *(const float4*)&A[(size_t)(m0 + row) * K + k0 + c4];
            Ash[c4 + 0][row] = v.x;
            Ash[c4 + 1][row] = v.y;
            Ash[c4 + 2][row] = v.z;
            Ash[c4 + 3][row] = v.w;
        }
        // B tile: 16 rows x 128 cols = 512 float4, 2 per thread
#pragma unroll
        for (int i = 0; i < 2; i++) {
            int f4 = tid + i * 256;
            int row = f4 >> 5;
            int c4 = (f4 & 31) * 4;
            *(float4*)&Bsh[row][c4] =
                *(const float4*)&Bm[(size_t)(k0 + row) * N + n0 + c4];
        }
        __syncthreads();

#pragma unroll
        for (int k = 0; k < 16; k++) {
            float a[8];
            *(float4*)&a[0] = *(const float4*)&Ash[k][ty * 8];
            *(float4*)&a[4] = *(const float4*)&Ash[k][ty * 8 + 4];
            const unsigned long long* bp =
                (const unsigned long long*)&Bsh[k][tx * 8];
            unsigned long long b0 = bp[0], b1 = bp[1], b2 = bp[2], b3 = bp[3];
#pragma unroll
            for (int i = 0; i < 8; i++) {
                unsigned long long as = splat2(a[i]);
                fma2(acc[i][0], as, b0);
                fma2(acc[i][1], as, b1);
                fma2(acc[i][2], as, b2);
                fma2(acc[i][3], as, b3);
            }
        }
        __syncthreads();
    }

    // epilogue: + bias, store
    float bv[8];
    *(float4*)&bv[0] = *(const float4*)&bias[n0 + tx * 8];
    *(float4*)&bv[4] = *(const float4*)&bias[n0 + tx * 8 + 4];
#pragma unroll
    for (int i = 0; i < 8; i++) {
        int row = m0 + ty * 8 + i;
        float o[8];
#pragma unroll
        for (int p = 0; p < 4; p++) {
            o[2 * p]     = lo2(acc[i][p]) + bv[2 * p];
            o[2 * p + 1] = hi2(acc[i][p]) + bv[2 * p + 1];
        }
        float* cp = &C[(size_t)row * N + n0 + tx * 8];
        *(float4*)&cp[0] = make_float4(o[0], o[1], o[2], o[3]);
        *(float4*)&cp[4] = make_float4(o[4], o[5], o[6], o[7]);
    }
}

// ---------------- fused LSTM step ------------------------------------------
// One step t: z = xz[:,t,:] + h_in @ R;  gate update; write h_out, c, hs[:,t,:].
// grid = 128 blocks: block bx owns hidden cols [8*bx, 8*bx+8) across ALL 4 gates.
// 256 threads: thread = (tb batch-quad, tu hidden-col). acc pairs: (i,f),(g,o).
__global__ __launch_bounds__(256) void lstm_step_kernel(
    const float* __restrict__ R, int t) {
    __shared__ float Hsh[32][132];    // [k][b] transposed h tile
    __shared__ float Rsh[32][8][4];   // [k][j][gate]  gates adjacent -> f32x2 pairs

    const int tid = threadIdx.x;
    const int c0 = blockIdx.x * 8;    // hidden-col base
    const int tu = tid & 7;           // j in [0,8)
    const int tb = (tid >> 3) * 4;    // batch base, 4 rows per thread

    const float* __restrict__ h_in = g_h[t & 1];
    float* __restrict__ h_out = g_h[(t + 1) & 1];

    unsigned long long acc[4][2];
#pragma unroll
    for (int i = 0; i < 4; i++) { acc[i][0] = 0ULL; acc[i][1] = 0ULL; }

    for (int k0 = 0; k0 < UU; k0 += 32) {
        // h tile: 128 b x 32 k = 1024 float4 -> 4 per thread, transposed store
#pragma unroll
        for (int i = 0; i < 4; i++) {
            int f4 = tid + i * 256;
            int b = f4 >> 3;
            int c4 = (f4 & 7) * 4;
            float4 v = *(const float4*)&h_in[b * UU + k0 + c4];
            Hsh[c4 + 0][b] = v.x;
            Hsh[c4 + 1][b] = v.y;
            Hsh[c4 + 2][b] = v.z;
            Hsh[c4 + 3][b] = v.w;
        }
        // R tile: 32 k x (8 j x 4 gates) = 1024 elems, j fastest for coalescing
#pragma unroll
        for (int i = 0; i < 4; i++) {
            int e = tid + i * 256;
            int k = e >> 5;
            int g = (e >> 3) & 3;
            int j = e & 7;
            Rsh[k][j][g] = R[(size_t)(k0 + k) * GG + g * UU + c0 + j];
        }
        __syncthreads();

#pragma unroll
        for (int k = 0; k < 32; k++) {
            float a[4];
            *(float4*)a = *(const float4*)&Hsh[k][tb];
            const unsigned long long* rp =
                (const unsigned long long*)&Rsh[k][tu][0];
            unsigned long long r0 = rp[0];   // (i,f) weights
            unsigned long long r1 = rp[1];   // (g,o) weights
#pragma unroll
            for (int i = 0; i < 4; i++) {
                unsigned long long as = splat2(a[i]);
                fma2(acc[i][0], as, r0);
                fma2(acc[i][1], as, r1);
            }
        }
        __syncthreads();
    }

    // gate update + state write
    const int u = c0 + tu;
#pragma unroll
    for (int i = 0; i < 4; i++) {
        int b = tb + i;
        size_t xzb = ((size_t)b * TT + t) * GG + u;
        float zi = lo2(acc[i][0]) + g_xz[xzb];
        float zf = hi2(acc[i][0]) + g_xz[xzb + UU];
        float zg = lo2(acc[i][1]) + g_xz[xzb + 2 * UU];
        float zo = hi2(acc[i][1]) + g_xz[xzb + 3 * UU];
        float ig = sigmoidf_(zi);
        float fg = sigmoidf_(zf);
        float og = sigmoidf_(zo);
        float gg = tanhf(zg);
        int su = b * UU + u;
        float cn = fg * g_c[su] + ig * gg;
        float hn = og * tanhf(cn);
        g_c[su] = cn;
        h_out[su] = hn;
        g_hs[((size_t)b * TT + t) * UU + u] = hn;
    }
}

// ---------------- host launcher --------------------------------------------
extern "C" void kernel_launch(void* const* d_in, const int* in_sizes, int n_in,
                              void* d_out, int out_size) {
    const float* x      = (const float*)d_in[0];  // [128,512,512]
    const float* h0     = (const float*)d_in[1];  // [128,1024]
    const float* c0     = (const float*)d_in[2];  // [128,1024]
    const float* kernel = (const float*)d_in[3];  // [512,4096]
    const float* rec    = (const float*)d_in[4];  // [1024,4096]
    const float* bias   = (const float*)d_in[5];  // [4096]
    const float* Wd     = (const float*)d_in[6];  // [1024,512]
    const float* bd     = (const float*)d_in[7];  // [512]
    float* out = (float*)d_out;                   // [128,512,512]

    void *p_xz = nullptr, *p_hs = nullptr;
    cudaGetSymbolAddress(&p_xz, g_xz);
    cudaGetSymbolAddress(&p_hs, g_hs);
    float* xz = (float*)p_xz;
    float* hs = (float*)p_hs;

    // 1) state init
    init_state<<<(BB * UU) / 256, 256>>>(h0, c0);

    // 2) xz = x @ kernel + bias   (M=65536, N=4096, K=512)
    {
        dim3 grid(GG / 128, (BB * TT) / 128);
        gemm_bias_kernel<<<grid, 256>>>(x, kernel, bias, xz, GG, DD);
    }

    // 3) sequential LSTM scan (stream-ordered launches = inter-step deps)
    for (int t = 0; t < TT; t++) {
        lstm_step_kernel<<<UU / 8, 256>>>(rec, t);
    }

    // 4) out = hs @ Wd + bd   (M=65536, N=512, K=1024)
    {
        dim3 grid(OO / 128, (BB * TT) / 128);
        gemm_bias_kernel<<<grid, 256>>>(hs, Wd, bd, out, OO, UU);
    }
}

// round 2
// speedup vs baseline: 1.3352x; 1.3352x over previous
#include <cuda_runtime.h>
#include <cstddef>
#include <cstdint>

// Problem dims (fixed by the benchmark)
#define BB 128
#define TT 512
#define DD 512
#define UU 1024
#define GG 4096   // 4*U
#define OO 512

#define NBLK 128        // persistent CTAs (<= SM count, all co-resident)
#define KT   64         // K-tile for h streaming
#define NT   (UU / KT)  // 16 tiles per step

typedef unsigned long long ull;

// ---------------- scratch (static device globals; no runtime allocation) ----
__device__ float g_xz[(size_t)BB * TT * GG];   // [B][T][4U] precomputed x@kernel+bias
__device__ float g_hs[(size_t)BB * TT * UU];   // [B][T][U]  all hidden states
__device__ float g_hT[2][UU * BB];             // transposed h, double-buffered: [u][b]
__device__ unsigned g_bar;                     // grid barrier counter (reset per launch)

// ---------------- packed f32x2 helpers (sm_10x) -----------------------------
__device__ __forceinline__ void fma2(ull &acc, ull a, ull b) {
    asm("fma.rn.f32x2 %0, %1, %2, %3;" : "=l"(acc) : "l"(a), "l"(b), "l"(acc));
}
__device__ __forceinline__ ull splat2(float x) {
    ull r; unsigned u = __float_as_uint(x);
    asm("mov.b64 %0, {%1, %1};" : "=l"(r) : "r"(u));
    return r;
}
__device__ __forceinline__ float lo2(ull v) { return __uint_as_float((unsigned)v); }
__device__ __forceinline__ float hi2(ull v) { return __uint_as_float((unsigned)(v >> 32)); }
__device__ __forceinline__ float sigmoidf_(float x) { return 1.0f / (1.0f + __expf(-x)); }

__device__ __forceinline__ void cp16(float* smem_dst, const float* gsrc) {
    unsigned ds = (unsigned)__cvta_generic_to_shared(smem_dst);
    asm volatile("cp.async.cg.shared.global [%0], [%1], 16;" :: "r"(ds), "l"(gsrc));
}
#define CP_COMMIT()  asm volatile("cp.async.commit_group;")
#define CP_WAIT(N)   asm volatile("cp.async.wait_group %0;" :: "n"(N))

// ---------------- init: transpose h0, reset barrier --------------------------
__global__ __launch_bounds__(256) void init_state(const float* __restrict__ h0) {
    int i = blockIdx.x * 256 + threadIdx.x;   // grid covers 128*1024
    int b = i / UU, u = i % UU;
    g_hT[0][u * BB + b] = h0[i];
    if (i == 0) g_bar = 0u;
}

// ---------------- generic GEMM: C[M,N] = A[M,K] @ B[K,N] + bias[N] ----------
__global__ __launch_bounds__(256) void gemm_bias_kernel(
    const float* __restrict__ A, const float* __restrict__ Bm,
    const float* __restrict__ bias, float* __restrict__ C,
    int N, int K) {
    __shared__ float Ash[16][132];
    __shared__ float Bsh[16][128];

    const int tid = threadIdx.x;
    const int m0 = blockIdx.y * 128;
    const int n0 = blockIdx.x * 128;
    const int tx = tid & 15;
    const int ty = tid >> 4;

    ull acc[8][4];
#pragma unroll
    for (int i = 0; i < 8; i++)
#pragma unroll
        for (int p = 0; p < 4; p++) acc[i][p] = 0ULL;

    for (int k0 = 0; k0 < K; k0 += 16) {
#pragma unroll
        for (int i = 0; i < 2; i++) {
            int f4 = tid + i * 256;
            int row = f4 >> 2;
            int c4 = (f4 & 3) * 4;
            float4 v = *(const float4*)&A[(size_t)(m0 + row) * K + k0 + c4];
            Ash[c4 + 0][row] = v.x;
            Ash[c4 + 1][row] = v.y;
            Ash[c4 + 2][row] = v.z;
            Ash[c4 + 3][row] = v.w;
        }
#pragma unroll
        for (int i = 0; i < 2; i++) {
            int f4 = tid + i * 256;
            int row = f4 >> 5;
            int c4 = (f4 & 31) * 4;
            *(float4*)&Bsh[row][c4] =
                *(const float4*)&Bm[(size_t)(k0 + row) * N + n0 + c4];
        }
        __syncthreads();

#pragma unroll
        for (int k = 0; k < 16; k++) {
            float a[8];
            *(float4*)&a[0] = *(const float4*)&Ash[k][ty * 8];
            *(float4*)&a[4] = *(const float4*)&Ash[k][ty * 8 + 4];
            const ull* bp = (const ull*)&Bsh[k][tx * 8];
            ull b0 = bp[0], b1 = bp[1], b2 = bp[2], b3 = bp[3];
#pragma unroll
            for (int i = 0; i < 8; i++) {
                ull as = splat2(a[i]);
                fma2(acc[i][0], as, b0);
                fma2(acc[i][1], as, b1);
                fma2(acc[i][2], as, b2);
                fma2(acc[i][3], as, b3);
            }
        }
        __syncthreads();
    }

    float bv[8];
    *(float4*)&bv[0] = *(const float4*)&bias[n0 + tx * 8];
    *(float4*)&bv[4] = *(const float4*)&bias[n0 + tx * 8 + 4];
#pragma unroll
    for (int i = 0; i < 8; i++) {
        int row = m0 + ty * 8 + i;
        float o[8];
#pragma unroll
        for (int p = 0; p < 4; p++) {
            o[2 * p]     = lo2(acc[i][p]) + bv[2 * p];
            o[2 * p + 1] = hi2(acc[i][p]) + bv[2 * p + 1];
        }
        float* cp = &C[(size_t)row * N + n0 + tx * 8];
        *(float4*)&cp[0] = make_float4(o[0], o[1], o[2], o[3]);
        *(float4*)&cp[4] = make_float4(o[4], o[5], o[6], o[7]);
    }
}

// ---------------- persistent LSTM scan --------------------------------------
// 128 CTAs, 1/SM, all co-resident. Block bx owns hidden cols [8*bx, 8*bx+8)
// across all 4 gates; its R slice (1024 x 8 x 4 = 131KB) stays in smem for
// the entire 512-step scan. c state lives in registers. h exchanged via
// transposed global buffers (contiguous cp.async tiles). Grid barrier
// between steps (monotonic counter, reset by init_state each launch).
__global__ __launch_bounds__(256, 1) void lstm_scan_kernel(
    const float* __restrict__ R, const float* __restrict__ c0in) {
    extern __shared__ float smem[];
    float* Rs = smem;              // [1024][8][4]  (k, j, gate)
    float* Hs = smem + UU * 32;    // [2][KT][128]  (buf, k, b)

    const int tid = threadIdx.x;
    const int u0 = blockIdx.x * 8;
    const int tu = tid & 7;          // hidden col within slice
    const int tb = (tid >> 3) * 4;   // batch base (4 rows per thread)
    const int u  = u0 + tu;

    // one-time R slice load: coalesced-ish LDG, scattered STS
    for (int e = tid; e < UU * 32; e += 256) {
        int j = e & 7, g = (e >> 3) & 3, k = e >> 5;
        Rs[k * 32 + j * 4 + g] = R[(size_t)k * GG + g * UU + u0 + j];
    }

    // c state in registers for the whole scan
    float creg[4];
#pragma unroll
    for (int i = 0; i < 4; i++) creg[i] = c0in[(size_t)(tb + i) * UU + u];

    __syncthreads();

    for (int t = 0; t < TT; t++) {
        const float* hin = g_hT[t & 1];
        float* hout = g_hT[(t + 1) & 1];

        // issue tile 0 (8 float4 per thread, contiguous 32KB)
        {
            float* dst = Hs;                       // buf 0
            const float* src = hin;                // kt = 0
#pragma unroll
            for (int w = 0; w < 8; w++) {
                int f = tid + w * 256;
                cp16(dst + f * 4, src + f * 4);
            }
            CP_COMMIT();
        }

        // prefetch xz gate biases for this step (completes during compute)
        float xzv[4][4];
#pragma unroll
        for (int i = 0; i < 4; i++) {
            const float* p = &g_xz[((size_t)(tb + i) * TT + t) * GG + u];
#pragma unroll
            for (int g = 0; g < 4; g++) xzv[i][g] = p[(size_t)g * UU];
        }

        ull acc[4][2];
#pragma unroll
        for (int i = 0; i < 4; i++) { acc[i][0] = 0ULL; acc[i][1] = 0ULL; }

        int buf = 0;
        for (int kt = 0; kt < NT; kt++) {
            if (kt + 1 < NT) {
                float* dst = Hs + (buf ^ 1) * (KT * BB);
                const float* src = hin + (kt + 1) * (KT * BB);
#pragma unroll
                for (int w = 0; w < 8; w++) {
                    int f = tid + w * 256;
                    cp16(dst + f * 4, src + f * 4);
                }
                CP_COMMIT();
                CP_WAIT(1);
            } else {
                CP_WAIT(0);
            }
            __syncthreads();

            const float* hb = Hs + buf * (KT * BB) + tb;
            const float* rb = Rs + (kt * KT) * 32 + tu * 4;
#pragma unroll 8
            for (int k = 0; k < KT; k++) {
                float4 hv = *(const float4*)&hb[k * BB];
                ulonglong2 rr = *(const ulonglong2*)&rb[k * 32];
                ull a0 = splat2(hv.x), a1 = splat2(hv.y);
                ull a2 = splat2(hv.z), a3 = splat2(hv.w);
                fma2(acc[0][0], a0, rr.x); fma2(acc[0][1], a0, rr.y);
                fma2(acc[1][0], a1, rr.x); fma2(acc[1][1], a1, rr.y);
                fma2(acc[2][0], a2, rr.x); fma2(acc[2][1], a2, rr.y);
                fma2(acc[3][0], a3, rr.x); fma2(acc[3][1], a3, rr.y);
            }
            __syncthreads();
            buf ^= 1;
        }

        // gate update + state write (c stays in registers)
#pragma unroll
        for (int i = 0; i < 4; i++) {
            float zi = lo2(acc[i][0]) + xzv[i][0];
            float zf = hi2(acc[i][0]) + xzv[i][1];
            float zg = lo2(acc[i][1]) + xzv[i][2];
            float zo = hi2(acc[i][1]) + xzv[i][3];
            float ig = sigmoidf_(zi);
            float fg = sigmoidf_(zf);
            float og = sigmoidf_(zo);
            float gg = tanhf(zg);
            float cn = fg * creg[i] + ig * gg;
            float hn = og * tanhf(cn);
            creg[i] = cn;
            hout[u * BB + tb + i] = hn;
            g_hs[((size_t)(tb + i) * TT + t) * UU + u] = hn;
        }

        // grid barrier (CG-style): sync, fence+arrive by t0, acquire-spin, sync
        __syncthreads();
        if (tid == 0) {
            __threadfence();
            atomicAdd(&g_bar, 1u);
            unsigned target = (unsigned)(t + 1) * NBLK;
            unsigned v;
            do {
                asm volatile("ld.global.acquire.gpu.u32 %0, [%1];"
                             : "=r"(v) : "l"(&g_bar) : "memory");
                if (v < target) __nanosleep(64);
            } while (v < target);
        }
        __syncthreads();
    }
}

// ---------------- host launcher --------------------------------------------
extern "C" void kernel_launch(void* const* d_in, const int* in_sizes, int n_in,
                              void* d_out, int out_size) {
    const float* x      = (const float*)d_in[0];  // [128,512,512]
    const float* h0     = (const float*)d_in[1];  // [128,1024]
    const float* c0in   = (const float*)d_in[2];  // [128,1024]
    const float* kernel = (const float*)d_in[3];  // [512,4096]
    const float* rec    = (const float*)d_in[4];  // [1024,4096]
    const float* bias   = (const float*)d_in[5];  // [4096]
    const float* Wd     = (const float*)d_in[6];  // [1024,512]
    const float* bd     = (const float*)d_in[7];  // [512]
    float* out = (float*)d_out;                   // [128,512,512]

    void *p_xz = nullptr, *p_hs = nullptr;
    cudaGetSymbolAddress(&p_xz, g_xz);
    cudaGetSymbolAddress(&p_hs, g_hs);
    float* xz = (float*)p_xz;
    float* hs = (float*)p_hs;

    const int scan_smem = (UU * 32 + 2 * KT * BB) * sizeof(float);  // 196608 B
    static bool attr_done = false;
    if (!attr_done) {
        cudaFuncSetAttribute(lstm_scan_kernel,
                             cudaFuncAttributeMaxDynamicSharedMemorySize,
                             scan_smem);
        attr_done = true;
    }

    // 1) state init (transposed h0) + barrier reset
    init_state<<<(BB * UU) / 256, 256>>>(h0);

    // 2) xz = x @ kernel + bias   (M=65536, N=4096, K=512)
    {
        dim3 grid(GG / 128, (BB * TT) / 128);
        gemm_bias_kernel<<<grid, 256>>>(x, kernel, bias, xz, GG, DD);
    }

    // 3) persistent LSTM scan (single kernel, 512 steps inside)
    lstm_scan_kernel<<<NBLK, 256, scan_smem>>>(rec, c0in);

    // 4) out = hs @ Wd + bd   (M=65536, N=512, K=1024)
    {
        dim3 grid(OO / 128, (BB * TT) / 128);
        gemm_bias_kernel<<<grid, 256>>>(hs, Wd, bd, out, OO, UU);
    }
}

// round 4
// speedup vs baseline: 1.6614x; 1.2443x over previous
#include <cuda_runtime.h>
#include <cuda_bf16.h>
#include <cstddef>
#include <cstdint>

// Problem dims (fixed by the benchmark)
#define BB 128
#define TT 512
#define DD 512
#define UU 1024
#define GG 4096   // 4*U
#define OO 512
#define MM (BB * TT)   // 65536

#define NBLK 128        // persistent CTAs for scan
#define KT   64         // K-tile for h streaming in scan
#define NT   (UU / KT)

typedef unsigned long long ull;
typedef __nv_bfloat16 bf16;

// ---------------- scratch (static device globals; no runtime allocation) ----
__device__ float g_xz[(size_t)MM * GG];        // [B*T][4U]
__device__ float g_hs[(size_t)MM * UU];        // [B*T][U]
__device__ float g_hT[2][UU * BB];             // transposed h, double-buffered
__device__ unsigned g_bar;                     // grid barrier counter

// split-bf16 K-tripled operands:  A3=[Ah|Ah|Al], B3=[Bh|Bl|Bh]
__device__ bf16 g_a3x[(size_t)MM * 3 * DD];    // x      -> [M][1536]
__device__ bf16 g_a3h[(size_t)MM * 3 * UU];    // hs     -> [M][3072]
__device__ bf16 g_b3k[(size_t)GG * 3 * DD];    // kernel^T -> [4096][1536]
__device__ bf16 g_b3w[(size_t)OO * 3 * UU];    // Wd^T     -> [512][3072]

// ---------------- small helpers --------------------------------------------
__device__ __forceinline__ void fma2(ull &acc, ull a, ull b) {
    asm("fma.rn.f32x2 %0, %1, %2, %3;" : "=l"(acc) : "l"(a), "l"(b), "l"(acc));
}
__device__ __forceinline__ ull splat2(float x) {
    ull r; unsigned u = __float_as_uint(x);
    asm("mov.b64 %0, {%1, %1};" : "=l"(r) : "r"(u));
    return r;
}
__device__ __forceinline__ float lo2(ull v) { return __uint_as_float((unsigned)v); }
__device__ __forceinline__ float hi2(ull v) { return __uint_as_float((unsigned)(v >> 32)); }
__device__ __forceinline__ float sigmoidf_(float x) { return 1.0f / (1.0f + __expf(-x)); }

__device__ __forceinline__ void cp16g(float* smem_dst, const float* gsrc) {
    unsigned ds = (unsigned)__cvta_generic_to_shared(smem_dst);
    asm volatile("cp.async.cg.shared.global [%0], [%1], 16;" :: "r"(ds), "l"(gsrc));
}
__device__ __forceinline__ void cp16s(uint32_t daddr, const void* g) {
    asm volatile("cp.async.cg.shared.global [%0], [%1], 16;" :: "r"(daddr), "l"(g));
}
#define CP_COMMIT()  asm volatile("cp.async.commit_group;")
#define CP_WAIT(N)   asm volatile("cp.async.wait_group %0;" :: "n"(N))

__device__ __forceinline__ void ldsm_x4(uint32_t &r0, uint32_t &r1,
                                        uint32_t &r2, uint32_t &r3, uint32_t a) {
    asm volatile("ldmatrix.sync.aligned.m8n8.x4.shared.b16 {%0,%1,%2,%3}, [%4];"
                 : "=r"(r0), "=r"(r1), "=r"(r2), "=r"(r3) : "r"(a));
}
__device__ __forceinline__ void mma16816(float* d, const uint32_t* a,
                                         const uint32_t* b) {
    asm volatile(
        "mma.sync.aligned.m16n8k16.row.col.f32.bf16.bf16.f32 "
        "{%0,%1,%2,%3}, {%4,%5,%6,%7}, {%8,%9}, {%0,%1,%2,%3};"
        : "+f"(d[0]), "+f"(d[1]), "+f"(d[2]), "+f"(d[3])
        : "r"(a[0]), "r"(a[1]), "r"(a[2]), "r"(a[3]), "r"(b[0]), "r"(b[1]));
}
__device__ __forceinline__ uint32_t swz(uint32_t o) { return o ^ ((o >> 3) & 0x70); }

// ---------------- prep kernels ----------------------------------------------
__global__ __launch_bounds__(256) void init_state(const float* __restrict__ h0) {
    int i = blockIdx.x * 256 + threadIdx.x;
    int b = i / UU, u = i % UU;
    g_hT[0][u * BB + b] = h0[i];
    if (i == 0) g_bar = 0u;
}

// in [M][K] fp32 -> out [M][3K] bf16: [Ah | Ah | Al]
__global__ __launch_bounds__(256) void split_pack_rows(
    const float* __restrict__ in, bf16* __restrict__ out, int K) {
    size_t i = (size_t)blockIdx.x * 256 + threadIdx.x;
    int m = (int)(i / K), k = (int)(i % K);
    float v = in[i];
    bf16 h = __float2bfloat16(v);
    bf16 l = __float2bfloat16(v - __bfloat162float(h));
    bf16* o = out + (size_t)m * 3 * K;
    o[k] = h; o[K + k] = h; o[2 * K + k] = l;
}

// in [K][N] fp32 -> out [N][3K] bf16: [Bh | Bl | Bh]
__global__ __launch_bounds__(256) void split_pack_T(
    const float* __restrict__ in, bf16* __restrict__ out, int K, int N) {
    size_t i = (size_t)blockIdx.x * 256 + threadIdx.x;
    if (i >= (size_t)K * N) return;
    int k = (int)(i / N), n = (int)(i % N);
    float v = in[i];
    bf16 h = __float2bfloat16(v);
    bf16 l = __float2bfloat16(v - __bfloat162float(h));
    bf16* o = out + (size_t)n * 3 * K;
    o[k] = h; o[K + k] = l; o[2 * K + k] = h;
}

// ---------------- mma.sync bf16 GEMM ----------------------------------------
// C[M,N] = A3[M,K3] @ B3[N,K3]^T + bias[N]   (fp32 accum, HMMA.16816)
// tile 128x128, KC=64, double-buffered cp.async, SW128 swizzle.
// 8 warps: warp (wm in 0..1, wn in 0..3) owns 64x32.
#define MMASM (2 * 32768)   // 2 bufs x (A 16KB + B 16KB)

__global__ __launch_bounds__(256, 1) void mma_gemm(
    const bf16* __restrict__ A3, const bf16* __restrict__ B3,
    const float* __restrict__ bias, float* __restrict__ C, int K3, int N) {
    extern __shared__ char smc[];
    const uint32_t sbase = (uint32_t)__cvta_generic_to_shared(smc);
    const int tid = threadIdx.x;
    const int wid = tid >> 5, lid = tid & 31;
    const int n0 = blockIdx.x * 128;
    const int m0 = blockIdx.y * 128;
    const int wm = (wid & 1) * 64;       // warp M base in tile
    const int wn = (wid >> 1) * 32;      // warp N base in tile
    const int nch = K3 / 64;

    float d[4][4][4];
#pragma unroll
    for (int i = 0; i < 4; i++)
#pragma unroll
        for (int j = 0; j < 4; j++)
#pragma unroll
            for (int q = 0; q < 4; q++) d[i][j][q] = 0.0f;

    // cp.async address pieces (per thread loads 4 x 16B for A and for B)
    const int r = tid >> 1;              // 0..127 rows (2 chunks per thread x4)
    // simpler: element e = tid + i*256: row = e>>3, chunk = e&7

    auto load_chunk = [&](int buf, int k0) {
        uint32_t ab = sbase + buf * 32768;
        uint32_t bb = ab + 16384;
#pragma unroll
        for (int i = 0; i < 4; i++) {
            int e = tid + i * 256;                 // 0..1023
            int rr = e >> 3, c8 = e & 7;
            uint32_t off = swz((uint32_t)(rr * 128 + c8 * 16));
            cp16s(ab + off, A3 + (size_t)(m0 + rr) * K3 + k0 + c8 * 8);
            cp16s(bb + off, B3 + (size_t)(n0 + rr) * K3 + k0 + c8 * 8);
        }
    };

    load_chunk(0, 0);
    CP_COMMIT();

    int buf = 0;
    for (int c = 0; c < nch; c++) {
        if (c + 1 < nch) {
            load_chunk(buf ^ 1, (c + 1) * 64);
            CP_COMMIT();
            CP_WAIT(1);
        } else {
            CP_WAIT(0);
        }
        __syncthreads();

        const uint32_t ab = sbase + buf * 32768;
        const uint32_t bb = ab + 16384;
#pragma unroll
        for (int kk = 0; kk < 64; kk += 16) {
            uint32_t af[4][4];
#pragma unroll
            for (int mi = 0; mi < 4; mi++) {
                uint32_t off = (uint32_t)((wm + mi * 16 + (lid & 15)) * 128
                                          + kk * 2 + (lid >> 4) * 16);
                ldsm_x4(af[mi][0], af[mi][1], af[mi][2], af[mi][3], ab + swz(off));
            }
            uint32_t bf_[4][2];
#pragma unroll
            for (int ni = 0; ni < 2; ni++) {
                int sub = lid >> 3;
                uint32_t off = (uint32_t)((wn + ni * 16 + ((sub >> 1) & 1) * 8
                                           + (lid & 7)) * 128
                                          + kk * 2 + (sub & 1) * 16);
                ldsm_x4(bf_[ni * 2][0], bf_[ni * 2][1],
                        bf_[ni * 2 + 1][0], bf_[ni * 2 + 1][1], bb + swz(off));
            }
#pragma unroll
            for (int mi = 0; mi < 4; mi++)
#pragma unroll
                for (int nf = 0; nf < 4; nf++)
                    mma16816(d[mi][nf], af[mi], bf_[nf]);
        }
        __syncthreads();
        buf ^= 1;
    }

    // epilogue: D + bias -> C
    const int lr = lid >> 2;             // 0..7
    const int lc = (lid & 3) * 2;        // 0,2,4,6
#pragma unroll
    for (int mi = 0; mi < 4; mi++) {
#pragma unroll
        for (int nf = 0; nf < 4; nf++) {
            int col = n0 + wn + nf * 8 + lc;
            float b0 = bias[col], b1 = bias[col + 1];
            int row0 = m0 + wm + mi * 16 + lr;
            float2 v0 = make_float2(d[mi][nf][0] + b0, d[mi][nf][1] + b1);
            float2 v1 = make_float2(d[mi][nf][2] + b0, d[mi][nf][3] + b1);
            *(float2*)&C[(size_t)row0 * N + col] = v0;
            *(float2*)&C[(size_t)(row0 + 8) * N + col] = v1;
        }
    }
}

// ---------------- persistent LSTM scan (unchanged from R2) ------------------
__global__ __launch_bounds__(256, 1) void lstm_scan_kernel(
    const float* __restrict__ R, const float* __restrict__ c0in) {
    extern __shared__ float smem[];
    float* Rs = smem;              // [1024][8][4]
    float* Hs = smem + UU * 32;    // [2][KT][128]

    const int tid = threadIdx.x;
    const int u0 = blockIdx.x * 8;
    const int tu = tid & 7;
    const int tb = (tid >> 3) * 4;
    const int u  = u0 + tu;

    for (int e = tid; e < UU * 32; e += 256) {
        int j = e & 7, g = (e >> 3) & 3, k = e >> 5;
        Rs[k * 32 + j * 4 + g] = R[(size_t)k * GG + g * UU + u0 + j];
    }

    float creg[4];
#pragma unroll
    for (int i = 0; i < 4; i++) creg[i] = c0in[(size_t)(tb + i) * UU + u];

    __syncthreads();

    for (int t = 0; t < TT; t++) {
        const float* hin = g_hT[t & 1];
        float* hout = g_hT[(t + 1) & 1];

        {
            float* dst = Hs;
            const float* src = hin;
#pragma unroll
            for (int w = 0; w < 8; w++) {
                int f = tid + w * 256;
                cp16g(dst + f * 4, src + f * 4);
            }
            CP_COMMIT();
        }

        float xzv[4][4];
#pragma unroll
        for (int i = 0; i < 4; i++) {
            const float* p = &g_xz[((size_t)(tb + i) * TT + t) * GG + u];
#pragma unroll
            for (int g = 0; g < 4; g++) xzv[i][g] = p[(size_t)g * UU];
        }

        ull acc[4][2];
#pragma unroll
        for (int i = 0; i < 4; i++) { acc[i][0] = 0ULL; acc[i][1] = 0ULL; }

        int buf = 0;
        for (int kt = 0; kt < NT; kt++) {
            if (kt + 1 < NT) {
                float* dst = Hs + (buf ^ 1) * (KT * BB);
                const float* src = hin + (kt + 1) * (KT * BB);
#pragma unroll
                for (int w = 0; w < 8; w++) {
                    int f = tid + w * 256;
                    cp16g(dst + f * 4, src + f * 4);
                }
                CP_COMMIT();
                CP_WAIT(1);
            } else {
                CP_WAIT(0);
            }
            __syncthreads();

            const float* hb = Hs + buf * (KT * BB) + tb;
            const float* rb = Rs + (kt * KT) * 32 + tu * 4;
#pragma unroll 8
            for (int k = 0; k < KT; k++) {
                float4 hv = *(const float4*)&hb[k * BB];
                ulonglong2 rr = *(const ulonglong2*)&rb[k * 32];
                ull a0 = splat2(hv.x), a1 = splat2(hv.y);
                ull a2 = splat2(hv.z), a3 = splat2(hv.w);
                fma2(acc[0][0], a0, rr.x); fma2(acc[0][1], a0, rr.y);
                fma2(acc[1][0], a1, rr.x); fma2(acc[1][1], a1, rr.y);
                fma2(acc[2][0], a2, rr.x); fma2(acc[2][1], a2, rr.y);
                fma2(acc[3][0], a3, rr.x); fma2(acc[3][1], a3, rr.y);
            }
            __syncthreads();
            buf ^= 1;
        }

#pragma unroll
        for (int i = 0; i < 4; i++) {
            float zi = lo2(acc[i][0]) + xzv[i][0];
            float zf = hi2(acc[i][0]) + xzv[i][1];
            float zg = lo2(acc[i][1]) + xzv[i][2];
            float zo = hi2(acc[i][1]) + xzv[i][3];
            float ig = sigmoidf_(zi);
            float fg = sigmoidf_(zf);
            float og = sigmoidf_(zo);
            float gg = tanhf(zg);
            float cn = fg * creg[i] + ig * gg;
            float hn = og * tanhf(cn);
            creg[i] = cn;
            hout[u * BB + tb + i] = hn;
            g_hs[((size_t)(tb + i) * TT + t) * UU + u] = hn;
        }

        __syncthreads();
        if (tid == 0) {
            __threadfence();
            atomicAdd(&g_bar, 1u);
            unsigned target = (unsigned)(t + 1) * NBLK;
            unsigned v;
            do {
                asm volatile("ld.global.acquire.gpu.u32 %0, [%1];"
                             : "=r"(v) : "l"(&g_bar) : "memory");
                if (v < target) __nanosleep(64);
            } while (v < target);
        }
        __syncthreads();
    }
}

// ---------------- host launcher --------------------------------------------
extern "C" void kernel_launch(void* const* d_in, const int* in_sizes, int n_in,
                              void* d_out, int out_size) {
    const float* x      = (const float*)d_in[0];
    const float* h0     = (const float*)d_in[1];
    const float* c0in   = (const float*)d_in[2];
    const float* kernel = (const float*)d_in[3];
    const float* rec    = (const float*)d_in[4];
    const float* bias   = (const float*)d_in[5];
    const float* Wd     = (const float*)d_in[6];
    const float* bd     = (const float*)d_in[7];
    float* out = (float*)d_out;

    void *p_xz, *p_hs, *p_a3x, *p_a3h, *p_b3k, *p_b3w;
    cudaGetSymbolAddress(&p_xz, g_xz);
    cudaGetSymbolAddress(&p_hs, g_hs);
    cudaGetSymbolAddress(&p_a3x, g_a3x);
    cudaGetSymbolAddress(&p_a3h, g_a3h);
    cudaGetSymbolAddress(&p_b3k, g_b3k);
    cudaGetSymbolAddress(&p_b3w, g_b3w);

    const int scan_smem = (UU * 32 + 2 * KT * BB) * sizeof(float);
    static bool attr_done = false;
    if (!attr_done) {
        cudaFuncSetAttribute(lstm_scan_kernel,
                             cudaFuncAttributeMaxDynamicSharedMemorySize, scan_smem);
        cudaFuncSetAttribute(mma_gemm,
                             cudaFuncAttributeMaxDynamicSharedMemorySize, MMASM);
        attr_done = true;
    }

    // 1) state init + operand splits
    init_state<<<(BB * UU) / 256, 256>>>(h0);
    split_pack_rows<<<(size_t)MM * DD / 256, 256>>>(x, (bf16*)p_a3x, DD);
    split_pack_T<<<((size_t)DD * GG + 255) / 256, 256>>>(kernel, (bf16*)p_b3k, DD, GG);
    split_pack_T<<<((size_t)UU * OO + 255) / 256, 256>>>(Wd, (bf16*)p_b3w, UU, OO);

    // 2) xz = x @ kernel + bias  (HMMA split-bf16; M=65536, N=4096, K3=1536)
    {
        dim3 grid(GG / 128, MM / 128);
        mma_gemm<<<grid, 256, MMASM>>>((const bf16*)p_a3x, (const bf16*)p_b3k,
                                       bias, (float*)p_xz, 3 * DD, GG);
    }

    // 3) persistent LSTM scan
    lstm_scan_kernel<<<NBLK, 256, scan_smem>>>(rec, c0in);

    // 4) hs splits, then out = hs @ Wd + bd  (M=65536, N=512, K3=3072)
    split_pack_rows<<<(size_t)MM * UU / 256, 256>>>((const float*)p_hs,
                                                    (bf16*)p_a3h, UU);
    {
        dim3 grid(OO / 128, MM / 128);
        mma_gemm<<<grid, 256, MMASM>>>((const bf16*)p_a3h, (const bf16*)p_b3w,
                                       bd, out, 3 * UU, OO);
    }
}

// round 5
// speedup vs baseline: 3.1051x; 1.8689x over previous
#include <cuda_runtime.h>
#include <cuda_bf16.h>
#include <cstddef>
#include <cstdint>

// Problem dims (fixed by the benchmark)
#define BB 128
#define TT 512
#define DD 512
#define UU 1024
#define GG 4096   // 4*U
#define OO 512
#define MM (BB * TT)   // 65536

#define NBLK 128        // persistent CTAs for scan

typedef __nv_bfloat16 bf16;

// ---------------- scratch (static device globals; no runtime allocation) ----
__device__ float g_xz[(size_t)MM * GG];        // [B*T][4U]
__device__ unsigned g_bar;                     // grid barrier counter

// split-bf16 K-tripled operands:  A3=[Ah|Ah|Al], B3=[Bh|Bl|Bh]
__device__ bf16 g_a3x[(size_t)MM * 3 * DD];    // x        -> [M][1536]
__device__ bf16 g_a3h[(size_t)MM * 3 * UU];    // h states -> [M][3072] (written by scan)
__device__ bf16 g_b3k[(size_t)GG * 3 * DD];    // kernel^T -> [4096][1536]
__device__ bf16 g_b3w[(size_t)OO * 3 * UU];    // Wd^T     -> [512][3072]
__device__ bf16 g_h0[(size_t)BB * 3 * UU];     // h0 in [hi|hi|lo] layout

// ---------------- helpers ----------------------------------------------------
__device__ __forceinline__ float sigmoidf_(float x) { return 1.0f / (1.0f + __expf(-x)); }

__device__ __forceinline__ void cp16s(uint32_t daddr, const void* g) {
    asm volatile("cp.async.cg.shared.global [%0], [%1], 16;" :: "r"(daddr), "l"(g));
}
#define CP_COMMIT()  asm volatile("cp.async.commit_group;")
#define CP_WAIT(N)   asm volatile("cp.async.wait_group %0;" :: "n"(N))

__device__ __forceinline__ void ldsm_x4(uint32_t &r0, uint32_t &r1,
                                        uint32_t &r2, uint32_t &r3, uint32_t a) {
    asm volatile("ldmatrix.sync.aligned.m8n8.x4.shared.b16 {%0,%1,%2,%3}, [%4];"
                 : "=r"(r0), "=r"(r1), "=r"(r2), "=r"(r3) : "r"(a));
}
__device__ __forceinline__ void mma16816(float* d, const uint32_t* a,
                                         const uint32_t* b) {
    asm volatile(
        "mma.sync.aligned.m16n8k16.row.col.f32.bf16.bf16.f32 "
        "{%0,%1,%2,%3}, {%4,%5,%6,%7}, {%8,%9}, {%0,%1,%2,%3};"
        : "+f"(d[0]), "+f"(d[1]), "+f"(d[2]), "+f"(d[3])
        : "r"(a[0]), "r"(a[1]), "r"(a[2]), "r"(a[3]), "r"(b[0]), "r"(b[1]));
}
__device__ __forceinline__ uint32_t swz(uint32_t o) { return o ^ ((o >> 3) & 0x70); }
__device__ __forceinline__ uint32_t packbf(bf16 a, bf16 b) {
    uint16_t x = *(uint16_t*)&a, y = *(uint16_t*)&b;
    return (uint32_t)x | ((uint32_t)y << 16);
}

// ---------------- prep kernels ----------------------------------------------
__global__ __launch_bounds__(256) void init_state(const float* __restrict__ h0) {
    int i = blockIdx.x * 256 + threadIdx.x;   // covers 128*1024
    int b = i / UU, u = i % UU;
    float v = h0[i];
    bf16 h = __float2bfloat16(v);
    bf16 l = __float2bfloat16(v - __bfloat162float(h));
    bf16* o = g_h0 + (size_t)b * 3 * UU;
    o[u] = h; o[UU + u] = h; o[2 * UU + u] = l;
    if (i == 0) g_bar = 0u;
}

// in [M][K] fp32 -> out [M][3K] bf16: [Ah | Ah | Al]
__global__ __launch_bounds__(256) void split_pack_rows(
    const float* __restrict__ in, bf16* __restrict__ out, int K) {
    size_t i = (size_t)blockIdx.x * 256 + threadIdx.x;
    int m = (int)(i / K), k = (int)(i % K);
    float v = in[i];
    bf16 h = __float2bfloat16(v);
    bf16 l = __float2bfloat16(v - __bfloat162float(h));
    bf16* o = out + (size_t)m * 3 * K;
    o[k] = h; o[K + k] = h; o[2 * K + k] = l;
}

// in [K][N] fp32 -> out [N][3K] bf16: [Bh | Bl | Bh]
__global__ __launch_bounds__(256) void split_pack_T(
    const float* __restrict__ in, bf16* __restrict__ out, int K, int N) {
    size_t i = (size_t)blockIdx.x * 256 + threadIdx.x;
    if (i >= (size_t)K * N) return;
    int k = (int)(i / N), n = (int)(i % N);
    float v = in[i];
    bf16 h = __float2bfloat16(v);
    bf16 l = __float2bfloat16(v - __bfloat162float(h));
    bf16* o = out + (size_t)n * 3 * K;
    o[k] = h; o[K + k] = l; o[2 * K + k] = h;
}

// ---------------- mma.sync bf16 GEMM (unchanged from R4) --------------------
#define MMASM (2 * 32768)

__global__ __launch_bounds__(256, 1) void mma_gemm(
    const bf16* __restrict__ A3, const bf16* __restrict__ B3,
    const float* __restrict__ bias, float* __restrict__ C, int K3, int N) {
    extern __shared__ char smc[];
    const uint32_t sbase = (uint32_t)__cvta_generic_to_shared(smc);
    const int tid = threadIdx.x;
    const int wid = tid >> 5, lid = tid & 31;
    const int n0 = blockIdx.x * 128;
    const int m0 = blockIdx.y * 128;
    const int wm = (wid & 1) * 64;
    const int wn = (wid >> 1) * 32;
    const int nch = K3 / 64;

    float d[4][4][4];
#pragma unroll
    for (int i = 0; i < 4; i++)
#pragma unroll
        for (int j = 0; j < 4; j++)
#pragma unroll
            for (int q = 0; q < 4; q++) d[i][j][q] = 0.0f;

    auto load_chunk = [&](int buf, int k0) {
        uint32_t ab = sbase + buf * 32768;
        uint32_t bb = ab + 16384;
#pragma unroll
        for (int i = 0; i < 4; i++) {
            int e = tid + i * 256;
            int rr = e >> 3, c8 = e & 7;
            uint32_t off = swz((uint32_t)(rr * 128 + c8 * 16));
            cp16s(ab + off, A3 + (size_t)(m0 + rr) * K3 + k0 + c8 * 8);
            cp16s(bb + off, B3 + (size_t)(n0 + rr) * K3 + k0 + c8 * 8);
        }
    };

    load_chunk(0, 0);
    CP_COMMIT();

    int buf = 0;
    for (int c = 0; c < nch; c++) {
        if (c + 1 < nch) {
            load_chunk(buf ^ 1, (c + 1) * 64);
            CP_COMMIT();
            CP_WAIT(1);
        } else {
            CP_WAIT(0);
        }
        __syncthreads();

        const uint32_t ab = sbase + buf * 32768;
        const uint32_t bb = ab + 16384;
#pragma unroll
        for (int kk = 0; kk < 64; kk += 16) {
            uint32_t af[4][4];
#pragma unroll
            for (int mi = 0; mi < 4; mi++) {
                uint32_t off = (uint32_t)((wm + mi * 16 + (lid & 15)) * 128
                                          + kk * 2 + (lid >> 4) * 16);
                ldsm_x4(af[mi][0], af[mi][1], af[mi][2], af[mi][3], ab + swz(off));
            }
            uint32_t bf_[4][2];
#pragma unroll
            for (int ni = 0; ni < 2; ni++) {
                int sub = lid >> 3;
                uint32_t off = (uint32_t)((wn + ni * 16 + ((sub >> 1) & 1) * 8
                                           + (lid & 7)) * 128
                                          + kk * 2 + (sub & 1) * 16);
                ldsm_x4(bf_[ni * 2][0], bf_[ni * 2][1],
                        bf_[ni * 2 + 1][0], bf_[ni * 2 + 1][1], bb + swz(off));
            }
#pragma unroll
            for (int mi = 0; mi < 4; mi++)
#pragma unroll
                for (int nf = 0; nf < 4; nf++)
                    mma16816(d[mi][nf], af[mi], bf_[nf]);
        }
        __syncthreads();
        buf ^= 1;
    }

    const int lr = lid >> 2;
    const int lc = (lid & 3) * 2;
#pragma unroll
    for (int mi = 0; mi < 4; mi++) {
#pragma unroll
        for (int nf = 0; nf < 4; nf++) {
            int col = n0 + wn + nf * 8 + lc;
            float b0 = bias[col], b1 = bias[col + 1];
            int row0 = m0 + wm + mi * 16 + lr;
            float2 v0 = make_float2(d[mi][nf][0] + b0, d[mi][nf][1] + b1);
            float2 v1 = make_float2(d[mi][nf][2] + b0, d[mi][nf][3] + b1);
            *(float2*)&C[(size_t)row0 * N + col] = v0;
            *(float2*)&C[(size_t)(row0 + 8) * N + col] = v1;
        }
    }
}

// ---------------- persistent MMA LSTM scan -----------------------------------
// 128 CTAs. CTA bx owns hidden cols [8bx, 8bx+8) x 4 gates (N=32, col n=gate*8+j).
// R slice resident in smem as split-bf16 (Rh+Rl), 16 swizzled [32][64] chunks.
// Per step: z = xz + h@R via 3-term HMMA (Ah*Rh + Ah*Rl + Al*Rh), fp32 accum.
// h_t written directly as [hi|hi|lo] rows of g_a3h (A operand of step t+1 AND
// of the final projection GEMM). c lives in registers. Grid barrier per step.
#define SC_RH 0
#define SC_RL 65536
#define SC_A  131072
#define SCANSM (SC_A + 2 * 32768)   // 196608

__global__ __launch_bounds__(256, 1) void lstm_scan_mma(
    const float* __restrict__ R, const float* __restrict__ c0in) {
    extern __shared__ char smc[];
    const uint32_t sb = (uint32_t)__cvta_generic_to_shared(smc);
    const int tid = threadIdx.x;
    const int wid = tid >> 5, lid = tid & 31;
    const int u0 = blockIdx.x * 8;
    const int wm = wid * 16;

    // ---- one-time: R slice -> smem split-bf16, swizzled chunks ----
    for (int e = tid; e < 32 * UU; e += 256) {
        int n = e & 31, k = e >> 5;
        int gate = n >> 3, j = n & 7;
        float v = R[(size_t)k * GG + gate * UU + u0 + j];
        bf16 h = __float2bfloat16(v);
        bf16 l = __float2bfloat16(v - __bfloat162float(h));
        uint32_t off = (uint32_t)((k >> 6) * 4096) + swz((uint32_t)(n * 128 + (k & 63) * 2));
        *(bf16*)(smc + SC_RH + off) = h;
        *(bf16*)(smc + SC_RL + off) = l;
    }

    // thread's (b,u) combos — fixed for the whole scan
    const int lr = lid >> 2, lc = (lid & 3) * 2;
    const int b1 = wm + lr, b2 = b1 + 8;
    const int bs_[4] = {b1, b1, b2, b2};
    const int uj_[4] = {lc, lc + 1, lc, lc + 1};

    float creg[4];
#pragma unroll
    for (int i = 0; i < 4; i++)
        creg[i] = c0in[(size_t)bs_[i] * UU + u0 + uj_[i]];

    __syncthreads();

    for (int t = 0; t < TT; t++) {
        // A source: h_{t-1} rows in [hi|hi|lo] layout
        const bf16* abase;
        size_t astride;
        if (t == 0) { abase = g_h0; astride = 3 * UU; }
        else        { abase = g_a3h + (size_t)(t - 1) * 3 * UU; astride = (size_t)TT * 3 * UU; }

        auto loadA = [&](int buf, int ck) {
            uint32_t ah = sb + SC_A + buf * 32768;
            uint32_t al = ah + 16384;
#pragma unroll
            for (int i = 0; i < 4; i++) {
                int e = tid + i * 256;              // 0..1023
                int rr = e >> 3, c8 = e & 7;
                uint32_t off = swz((uint32_t)(rr * 128 + c8 * 16));
                const bf16* rowp = abase + (size_t)rr * astride + ck * 64 + c8 * 8;
                cp16s(ah + off, rowp);              // hi (cols 0..1023)
                cp16s(al + off, rowp + 2 * UU);     // lo (cols 2048..3071)
            }
        };

        loadA(0, 0);
        CP_COMMIT();

        // prefetch xz for this step (16 scattered LDG, hidden under MMA)
        float xzv[4][4];
#pragma unroll
        for (int i = 0; i < 4; i++) {
            const float* p = &g_xz[((size_t)bs_[i] * TT + t) * GG + u0 + uj_[i]];
#pragma unroll
            for (int g = 0; g < 4; g++) xzv[i][g] = p[(size_t)g * UU];
        }

        float d[4][4];
#pragma unroll
        for (int f = 0; f < 4; f++)
#pragma unroll
            for (int q = 0; q < 4; q++) d[f][q] = 0.0f;

        int buf = 0;
        for (int ck = 0; ck < 16; ck++) {
            if (ck + 1 < 16) {
                loadA(buf ^ 1, ck + 1);
                CP_COMMIT();
                CP_WAIT(1);
            } else {
                CP_WAIT(0);
            }
            __syncthreads();

            const uint32_t ah = sb + SC_A + buf * 32768;
            const uint32_t al = ah + 16384;
            const uint32_t rh = sb + SC_RH + ck * 4096;
            const uint32_t rl = sb + SC_RL + ck * 4096;
#pragma unroll
            for (int kk = 0; kk < 64; kk += 16) {
                uint32_t offA = swz((uint32_t)((wm + (lid & 15)) * 128
                                               + kk * 2 + (lid >> 4) * 16));
                uint32_t afh[4], afl[4];
                ldsm_x4(afh[0], afh[1], afh[2], afh[3], ah + offA);
                ldsm_x4(afl[0], afl[1], afl[2], afl[3], al + offA);

                uint32_t bh[4][2], bl[4][2];
#pragma unroll
                for (int ni = 0; ni < 2; ni++) {
                    int sub = lid >> 3;
                    uint32_t offB = swz((uint32_t)((ni * 16 + ((sub >> 1) & 1) * 8
                                                    + (lid & 7)) * 128
                                                   + kk * 2 + (sub & 1) * 16));
                    ldsm_x4(bh[ni * 2][0], bh[ni * 2][1],
                            bh[ni * 2 + 1][0], bh[ni * 2 + 1][1], rh + offB);
                    ldsm_x4(bl[ni * 2][0], bl[ni * 2][1],
                            bl[ni * 2 + 1][0], bl[ni * 2 + 1][1], rl + offB);
                }
#pragma unroll
                for (int f = 0; f < 4; f++) {
                    mma16816(d[f], afh, bh[f]);
                    mma16816(d[f], afh, bl[f]);
                    mma16816(d[f], afl, bh[f]);
                }
            }
            __syncthreads();
            buf ^= 1;
        }

        // gate update: d[f][i] = gate f for combo i  (col n = f*8 + j)
        float hn[4];
#pragma unroll
        for (int i = 0; i < 4; i++) {
            float zi = d[0][i] + xzv[i][0];
            float zf = d[1][i] + xzv[i][1];
            float zg = d[2][i] + xzv[i][2];
            float zo = d[3][i] + xzv[i][3];
            float ig = sigmoidf_(zi);
            float fg = sigmoidf_(zf);
            float og = sigmoidf_(zo);
            float gg = tanhf(zg);
            float cn = fg * creg[i] + ig * gg;
            creg[i] = cn;
            hn[i] = og * tanhf(cn);
        }

        // write h_t as [hi|hi|lo] pairs (combos 0,1 share row b1; 2,3 share b2)
#pragma unroll
        for (int pp = 0; pp < 2; pp++) {
            int b = pp ? b2 : b1;
            float v0 = hn[pp * 2], v1 = hn[pp * 2 + 1];
            bf16 h0b = __float2bfloat16(v0);
            bf16 h1b = __float2bfloat16(v1);
            bf16 l0b = __float2bfloat16(v0 - __bfloat162float(h0b));
            bf16 l1b = __float2bfloat16(v1 - __bfloat162float(h1b));
            uint32_t hp = packbf(h0b, h1b), lp = packbf(l0b, l1b);
            bf16* rowp = g_a3h + ((size_t)b * TT + t) * 3 * UU + u0 + lc;
            *(uint32_t*)(rowp)          = hp;
            *(uint32_t*)(rowp + UU)     = hp;
            *(uint32_t*)(rowp + 2 * UU) = lp;
        }

        // grid barrier
        __syncthreads();
        if (tid == 0) {
            __threadfence();
            atomicAdd(&g_bar, 1u);
            unsigned target = (unsigned)(t + 1) * NBLK;
            unsigned v;
            do {
                asm volatile("ld.global.acquire.gpu.u32 %0, [%1];"
                             : "=r"(v) : "l"(&g_bar) : "memory");
                if (v < target) __nanosleep(64);
            } while (v < target);
        }
        __syncthreads();
    }
}

// ---------------- host launcher --------------------------------------------
extern "C" void kernel_launch(void* const* d_in, const int* in_sizes, int n_in,
                              void* d_out, int out_size) {
    const float* x      = (const float*)d_in[0];
    const float* h0     = (const float*)d_in[1];
    const float* c0in   = (const float*)d_in[2];
    const float* kernel = (const float*)d_in[3];
    const float* rec    = (const float*)d_in[4];
    const float* bias   = (const float*)d_in[5];
    const float* Wd     = (const float*)d_in[6];
    const float* bd     = (const float*)d_in[7];
    float* out = (float*)d_out;

    void *p_xz, *p_a3x, *p_a3h, *p_b3k, *p_b3w;
    cudaGetSymbolAddress(&p_xz, g_xz);
    cudaGetSymbolAddress(&p_a3x, g_a3x);
    cudaGetSymbolAddress(&p_a3h, g_a3h);
    cudaGetSymbolAddress(&p_b3k, g_b3k);
    cudaGetSymbolAddress(&p_b3w, g_b3w);

    static bool attr_done = false;
    if (!attr_done) {
        cudaFuncSetAttribute(lstm_scan_mma,
                             cudaFuncAttributeMaxDynamicSharedMemorySize, SCANSM);
        cudaFuncSetAttribute(mma_gemm,
                             cudaFuncAttributeMaxDynamicSharedMemorySize, MMASM);
        attr_done = true;
    }

    // 1) state init + operand splits
    init_state<<<(BB * UU) / 256, 256>>>(h0);
    split_pack_rows<<<(size_t)MM * DD / 256, 256>>>(x, (bf16*)p_a3x, DD);
    split_pack_T<<<((size_t)DD * GG + 255) / 256, 256>>>(kernel, (bf16*)p_b3k, DD, GG);
    split_pack_T<<<((size_t)UU * OO + 255) / 256, 256>>>(Wd, (bf16*)p_b3w, UU, OO);

    // 2) xz = x @ kernel + bias  (HMMA split-bf16; M=65536, N=4096, K3=1536)
    {
        dim3 grid(GG / 128, MM / 128);
        mma_gemm<<<grid, 256, MMASM>>>((const bf16*)p_a3x, (const bf16*)p_b3k,
                                       bias, (float*)p_xz, 3 * DD, GG);
    }

    // 3) persistent MMA LSTM scan (writes g_a3h directly)
    lstm_scan_mma<<<NBLK, 256, SCANSM>>>(rec, c0in);

    // 4) out = hs @ Wd + bd  (M=65536, N=512, K3=3072) — A3 comes from the scan
    {
        dim3 grid(OO / 128, MM / 128);
        mma_gemm<<<grid, 256, MMASM>>>((const bf16*)p_a3h, (const bf16*)p_b3w,
                                       bd, out, 3 * UU, OO);
    }
}